// round 13
// baseline (speedup 1.0000x reference)
#include <cuda_runtime.h>
#include <cuda_bf16.h>

// BlockAttnRes: per-token block attention over N=9 source rows of D=512.
//   score_n = dot(src_n, w) / sqrt(mean(src_n^2)+1e-6),  alpha = softmax(score),
//   h = sum_n alpha_n * src_n.
//
// R13 = R12/R9 structure (best @ 101.2us) at doubled CTA granularity:
// 256-thread CTAs process TWO independent tokens (threads 0-127 -> token
// 2b, threads 128-255 -> token 2b+1). Halves CTA launch/retire and
// prologue overhead; barriers are shared (both halves participate) so the
// barrier count per token is halved too. Per-token dataflow is byte-
// identical: register-resident rows, ldcs/stcs streaming hints, query
// load issued first, per-group first-warp parallel softmax.

#define NN 9
#define DD 512
#define THREADS 256
#define TPC 2          // tokens per CTA

__global__ __launch_bounds__(THREADS)
void blockattn_kernel(const float* __restrict__ src,
                      const float* __restrict__ queries,
                      const int*   __restrict__ layer_idx,
                      float*       __restrict__ out)
{
    const int tid  = threadIdx.x;
    const int lane = tid & 31;
    const int warp = tid >> 5;          // 0..7
    const int grp  = warp >> 2;         // 0 or 1: which token this thread works
    const int gw   = warp & 3;          // warp index within group (0..3)
    const int gt   = tid & 127;         // thread index within group

    const long long token = (long long)blockIdx.x * TPC + grp;
    const float4* base = reinterpret_cast<const float4*>(src + token * (long long)(NN * DD));

    // Query row (L2/L1-resident broadcast) — issued FIRST (R11 showed the
    // L1tex FIFO punishes putting it behind the source burst).
    const int li = *layer_idx;
    const float4 w4 = reinterpret_cast<const float4*>(queries + (long long)li * DD)[gt];

    // ---- Phase 1: load all 9 rows into registers (streaming, coalesced) ----
    float4 v[NN];
#pragma unroll
    for (int n = 0; n < NN; n++)
        v[n] = __ldcs(base + n * (DD / 4) + gt);

    // ---- Per-thread partials: sum of squares & dot with w, per row ----
    float ss[NN], dt[NN];
#pragma unroll
    for (int n = 0; n < NN; n++) {
        const float4 a = v[n];
        ss[n] = a.x * a.x + a.y * a.y + a.z * a.z + a.w * a.w;
        dt[n] = a.x * w4.x + a.y * w4.y + a.z * w4.z + a.w * w4.w;
    }

    // ---- Warp reduction ----
#pragma unroll
    for (int n = 0; n < NN; n++) {
#pragma unroll
        for (int o = 16; o > 0; o >>= 1) {
            ss[n] += __shfl_xor_sync(0xffffffffu, ss[n], o);
            dt[n] += __shfl_xor_sync(0xffffffffu, dt[n], o);
        }
    }

    // ---- Cross-warp reduction via shared (per token group) ----
    __shared__ float s_ss[TPC][NN][4];
    __shared__ float s_dt[TPC][NN][4];
    __shared__ float s_alpha[TPC][NN];

    if (lane == 0) {
#pragma unroll
        for (int n = 0; n < NN; n++) {
            s_ss[grp][n][gw] = ss[n];
            s_dt[grp][n][gw] = dt[n];
        }
    }
    __syncthreads();

    // ---- Softmax: first warp of each group, lane n owns row n ----
    if (gw == 0) {
        float sc = -3.4e38f;
        if (lane < NN) {
            const float S  = s_ss[grp][lane][0] + s_ss[grp][lane][1]
                           + s_ss[grp][lane][2] + s_ss[grp][lane][3];
            const float Dt = s_dt[grp][lane][0] + s_dt[grp][lane][1]
                           + s_dt[grp][lane][2] + s_dt[grp][lane][3];
            sc = Dt * rsqrtf(S * (1.0f / DD) + 1e-6f);
        }
        float mx = sc;
#pragma unroll
        for (int o = 16; o > 0; o >>= 1)
            mx = fmaxf(mx, __shfl_xor_sync(0xffffffffu, mx, o));

        float e = (lane < NN) ? __expf(sc - mx) : 0.0f;
        float sum = e;
#pragma unroll
        for (int o = 16; o > 0; o >>= 1)
            sum += __shfl_xor_sync(0xffffffffu, sum, o);

        if (lane < NN)
            s_alpha[grp][lane] = e / sum;
    }
    __syncthreads();

    // ---- Phase 2: weighted sum from register-resident rows ----
    float4 o = make_float4(0.f, 0.f, 0.f, 0.f);
#pragma unroll
    for (int n = 0; n < NN; n++) {
        const float a = s_alpha[grp][n];
        o.x += a * v[n].x;
        o.y += a * v[n].y;
        o.z += a * v[n].z;
        o.w += a * v[n].w;
    }

    __stcs(reinterpret_cast<float4*>(out + token * (long long)DD) + gt, o);
}

extern "C" void kernel_launch(void* const* d_in, const int* in_sizes, int n_in,
                              void* d_out, int out_size)
{
    const float* src     = (const float*)d_in[0];
    const float* queries = (const float*)d_in[1];
    const int*   lidx    = (const int*)d_in[2];
    float*       out     = (float*)d_out;

    const int tokens = in_sizes[0] / (NN * DD);   // B*T = 32768 (even)
    blockattn_kernel<<<tokens / TPC, THREADS>>>(src, queries, lidx, out);
}

// round 14
// speedup vs baseline: 1.0434x; 1.0434x over previous
#include <cuda_runtime.h>
#include <cuda_bf16.h>

// BlockAttnRes: per-token block attention over N=9 source rows of D=512.
//   score_n = dot(src_n, w) / sqrt(mean(src_n^2)+1e-6),  alpha = softmax(score),
//   h = sum_n alpha_n * src_n.
//
// FINAL — best of 13 measured variants (101.18us, 6.63 TB/s effective,
// DRAM-active 80.8% = this stream's empirical ceiling):
//   - one 128-thread CTA per token; 9 rows x float4/thread register-
//     resident; sources read from DRAM exactly once (compulsory 671 MB)
//   - query/layer_idx loads issue FIRST (L2-hit feeding the FMA chain;
//     placing them behind the source burst serializes on the L1tex FIFO
//     and cost +35us when tried)
//   - warp-0 parallel softmax (lane n owns row n), two barriers
//   - __ldcs/__stcs streaming hints on the zero-reuse streams
// Rejected by measurement: TMA+smem staging, register double-buffering,
// cp.async staging, persistent grids, L2 prefetch, launch-bounds forcing,
// fused/redundant/barrier-free softmax, load reordering, 2-tokens-per-CTA.

#define NN 9
#define DD 512
#define THREADS 128

__global__ __launch_bounds__(THREADS)
void blockattn_kernel(const float* __restrict__ src,
                      const float* __restrict__ queries,
                      const int*   __restrict__ layer_idx,
                      float*       __restrict__ out)
{
    const int tid  = threadIdx.x;
    const int lane = tid & 31;
    const int warp = tid >> 5;

    const long long token = blockIdx.x;
    const float4* base = reinterpret_cast<const float4*>(src + token * (long long)(NN * DD));

    // Query row (L2-resident, broadcast across all CTAs) — issued FIRST.
    const int li = *layer_idx;
    const float4 w4 = reinterpret_cast<const float4*>(queries + (long long)li * DD)[tid];

    // ---- Phase 1: load all 9 rows into registers (streaming, coalesced) ----
    float4 v[NN];
#pragma unroll
    for (int n = 0; n < NN; n++)
        v[n] = __ldcs(base + n * (DD / 4) + tid);

    // ---- Per-thread partials: sum of squares & dot with w, per row ----
    float ss[NN], dt[NN];
#pragma unroll
    for (int n = 0; n < NN; n++) {
        const float4 a = v[n];
        ss[n] = a.x * a.x + a.y * a.y + a.z * a.z + a.w * a.w;
        dt[n] = a.x * w4.x + a.y * w4.y + a.z * w4.z + a.w * w4.w;
    }

    // ---- Warp reduction ----
#pragma unroll
    for (int n = 0; n < NN; n++) {
#pragma unroll
        for (int o = 16; o > 0; o >>= 1) {
            ss[n] += __shfl_xor_sync(0xffffffffu, ss[n], o);
            dt[n] += __shfl_xor_sync(0xffffffffu, dt[n], o);
        }
    }

    // ---- Cross-warp reduction via shared ----
    __shared__ float s_ss[NN][4];
    __shared__ float s_dt[NN][4];
    __shared__ float s_alpha[NN];

    if (lane == 0) {
#pragma unroll
        for (int n = 0; n < NN; n++) {
            s_ss[n][warp] = ss[n];
            s_dt[n][warp] = dt[n];
        }
    }
    __syncthreads();

    // ---- Softmax on warp 0: lane n owns row n (parallel MUFU) ----
    if (warp == 0) {
        float sc = -3.4e38f;
        if (lane < NN) {
            const float S  = s_ss[lane][0] + s_ss[lane][1] + s_ss[lane][2] + s_ss[lane][3];
            const float Dt = s_dt[lane][0] + s_dt[lane][1] + s_dt[lane][2] + s_dt[lane][3];
            sc = Dt * rsqrtf(S * (1.0f / DD) + 1e-6f);
        }
        float mx = sc;
#pragma unroll
        for (int o = 16; o > 0; o >>= 1)
            mx = fmaxf(mx, __shfl_xor_sync(0xffffffffu, mx, o));

        float e = (lane < NN) ? __expf(sc - mx) : 0.0f;
        float sum = e;
#pragma unroll
        for (int o = 16; o > 0; o >>= 1)
            sum += __shfl_xor_sync(0xffffffffu, sum, o);

        if (lane < NN)
            s_alpha[lane] = e / sum;
    }
    __syncthreads();

    // ---- Phase 2: weighted sum from register-resident rows ----
    float4 o = make_float4(0.f, 0.f, 0.f, 0.f);
#pragma unroll
    for (int n = 0; n < NN; n++) {
        const float a = s_alpha[n];
        o.x += a * v[n].x;
        o.y += a * v[n].y;
        o.z += a * v[n].z;
        o.w += a * v[n].w;
    }

    __stcs(reinterpret_cast<float4*>(out + token * (long long)DD) + tid, o);
}

extern "C" void kernel_launch(void* const* d_in, const int* in_sizes, int n_in,
                              void* d_out, int out_size)
{
    const float* src     = (const float*)d_in[0];
    const float* queries = (const float*)d_in[1];
    const int*   lidx    = (const int*)d_in[2];
    float*       out     = (float*)d_out;

    const int tokens = in_sizes[0] / (NN * DD);   // B*T = 32768
    blockattn_kernel<<<tokens, THREADS>>>(src, queries, lidx, out);
}